// round 1
// baseline (speedup 1.0000x reference)
#include <cuda_runtime.h>
#include <cstdint>

#define B_   4
#define N_   2000
#define M_   2000
#define R_   8000      // B*N rows
#define K_   16
#define EMB_ 128
#define E2_  256
#define PENALTY_ (-10.0f)
#define EPS_ 1e-5f
#define TAU_ 0.05f
#define CAP_ 1024
#define NCH_ 32
#define CHUNK_ 63

// ---- scratch (static device globals: no runtime allocation) ----
__device__ float g_W1t[34 * 128];        // W1^T  [j][co]
__device__ float g_W2t[128 * 256];       // W2^T  [c][co]
__device__ float g_W3t[256 * 128];       // W3^T  [c][co]
__device__ float g_W4t[128 * 16];        // W4^T  [c][k]
__device__ float g_h2[(size_t)R_ * E2_]; // layer-2 activations (post-relu)
__device__ float g_sd[R_ * K_];          // normalized sorted dist
__device__ int   g_si[R_ * K_];          // sorted indices
__device__ float g_ps [B_ * NCH_ * E2_]; // partial sums
__device__ float g_pss[B_ * NCH_ * E2_]; // partial sum-of-squares
__device__ float g_scale[B_ * E2_];
__device__ float g_shift[B_ * E2_];

// ---- kernel T: transpose the four weight matrices ----
__global__ __launch_bounds__(256) void kT(const float* __restrict__ W1,
                                          const float* __restrict__ W2,
                                          const float* __restrict__ W3,
                                          const float* __restrict__ W4) {
  int t = blockIdx.x * blockDim.x + threadIdx.x;
  int stride = gridDim.x * blockDim.x;
  for (int o = t; o < 34 * 128; o += stride) { int co = o & 127, j = o >> 7; g_W1t[o] = W1[co * 34 + j]; }
  for (int o = t; o < 128 * 256; o += stride) { int co = o & 255, c = o >> 8; g_W2t[o] = W2[co * 128 + c]; }
  for (int o = t; o < 256 * 128; o += stride) { int co = o & 127, c = o >> 7; g_W3t[o] = W3[co * 256 + c]; }
  for (int o = t; o < 128 * 16;  o += stride) { int k  = o & 15,  c = o >> 4; g_W4t[o] = W4[k * 128 + c]; }
}

// ---- kernel A: per-row top-16 (threshold filter + warp select), layers 1-2 ----
__global__ __launch_bounds__(256) void kA(const float* __restrict__ theta,
                                          const float* __restrict__ dist,
                                          const float* __restrict__ insf,
                                          const float* __restrict__ b1,
                                          const float* __restrict__ b2) {
  int r = blockIdx.x;
  int tid = threadIdx.x;
  const float* drow = dist + (size_t)r * M_;

  __shared__ unsigned long long cand[CAP_];
  __shared__ int cnt;
  __shared__ float sds[K_];
  __shared__ int   sis[K_];
  __shared__ float xs[34];
  __shared__ float h1s[EMB_];
  __shared__ float4 p2[256];
  __shared__ unsigned long long wred[8];

  if (tid == 0) cnt = 0;
  __syncthreads();

  // ---- filter pass: candidates with dist < TAU (memory-bound full-row scan) ----
  #pragma unroll 4
  for (int i = tid; i < M_; i += 256) {
    float v = drow[i];
    if (v < TAU_) {
      int p = atomicAdd(&cnt, 1);
      if (p < CAP_)
        cand[p] = (((unsigned long long)__float_as_uint(v)) << 32) | (unsigned)i;
    }
  }
  __syncthreads();
  int C = cnt;

  if (C >= K_ && C <= CAP_) {
    // ---- fast path: warp 0 selects 16 smallest (packed (val,idx) is unique;
    //      "next-min strictly greater than last" needs no removal) ----
    if (tid < 32) {
      unsigned long long last = 0ULL;
      for (int k = 0; k < K_; k++) {
        unsigned long long m = ~0ULL;
        for (int j = tid; j < C; j += 32) {
          unsigned long long c = cand[j];
          if ((k == 0 || c > last) && c < m) m = c;
        }
        #pragma unroll
        for (int off = 16; off; off >>= 1) {
          unsigned long long o = __shfl_down_sync(0xffffffffu, m, off);
          m = (o < m) ? o : m;
        }
        m = __shfl_sync(0xffffffffu, m, 0);
        if (tid == 0) {
          sds[k] = __uint_as_float((unsigned)(m >> 32));
          sis[k] = (int)(unsigned)(m & 0xffffffffu);
        }
        last = m;
      }
    }
  } else {
    // ---- exact fallback (never taken on the benchmark data, guards correctness) ----
    unsigned long long last = 0ULL;
    int wid = tid >> 5, lane = tid & 31;
    for (int k = 0; k < K_; k++) {
      unsigned long long m = ~0ULL;
      for (int i = tid; i < M_; i += 256) {
        unsigned long long c =
            (((unsigned long long)__float_as_uint(drow[i])) << 32) | (unsigned)i;
        if ((k == 0 || c > last) && c < m) m = c;
      }
      #pragma unroll
      for (int off = 16; off; off >>= 1) {
        unsigned long long o = __shfl_down_sync(0xffffffffu, m, off);
        m = (o < m) ? o : m;
      }
      if (lane == 0) wred[wid] = m;
      __syncthreads();
      if (tid == 0) {
        m = wred[0];
        for (int w = 1; w < 8; w++) if (wred[w] < m) m = wred[w];
        wred[0] = m;
        sds[k] = __uint_as_float((unsigned)(m >> 32));
        sis[k] = (int)(unsigned)(m & 0xffffffffu);
      }
      __syncthreads();
      last = wred[0];
      __syncthreads();
    }
  }
  __syncthreads();

  // ---- build x = [sorted_dist/max, sorted_theta, ins0, ins1] ----
  if (tid < K_) {
    float maxd = sds[K_ - 1];
    float nd = sds[tid] / maxd;
    xs[tid] = nd;
    xs[K_ + tid] = theta[(size_t)r * M_ + sis[tid]];
    g_sd[r * K_ + tid] = nd;
    g_si[r * K_ + tid] = sis[tid];
  }
  if (tid == 32) xs[32] = insf[r];
  if (tid == 33) xs[33] = insf[R_ + r];
  __syncthreads();

  // ---- layer 1: 34 -> 128, relu ----
  if (tid < EMB_) {
    float acc = b1[tid];
    #pragma unroll
    for (int j = 0; j < 34; j++) acc = fmaf(xs[j], g_W1t[j * EMB_ + tid], acc);
    h1s[tid] = fmaxf(acc, 0.f);
  }
  __syncthreads();

  // ---- layer 2: 128 -> 256, relu (float4, 4 outputs/thread, 4 c-segments) ----
  {
    int og = tid & 63, seg = tid >> 6;
    const float4* W2t4 = reinterpret_cast<const float4*>(g_W2t);
    float4 acc = make_float4(0.f, 0.f, 0.f, 0.f);
    int c0 = seg * 32;
    #pragma unroll
    for (int cc = 0; cc < 32; cc++) {
      int c = c0 + cc;
      float h = h1s[c];
      float4 w = W2t4[c * 64 + og];
      acc.x = fmaf(h, w.x, acc.x);
      acc.y = fmaf(h, w.y, acc.y);
      acc.z = fmaf(h, w.z, acc.z);
      acc.w = fmaf(h, w.w, acc.w);
    }
    p2[tid] = acc;
  }
  __syncthreads();
  if (tid < 64) {
    float4 a = p2[tid], b = p2[tid + 64], c = p2[tid + 128], d = p2[tid + 192];
    float4 bb = reinterpret_cast<const float4*>(b2)[tid];
    float4 o;
    o.x = fmaxf(a.x + b.x + c.x + d.x + bb.x, 0.f);
    o.y = fmaxf(a.y + b.y + c.y + d.y + bb.y, 0.f);
    o.z = fmaxf(a.z + b.z + c.z + d.z + bb.z, 0.f);
    o.w = fmaxf(a.w + b.w + c.w + d.w + bb.w, 0.f);
    reinterpret_cast<float4*>(g_h2)[(size_t)r * 64 + tid] = o;
  }
}

// ---- kernel B1: chunked partial sums for InstanceNorm (deterministic) ----
__global__ __launch_bounds__(256) void kB1() {
  int ch = blockIdx.x, b = blockIdx.y, t = threadIdx.x;
  int n0 = ch * CHUNK_;
  int n1 = min(n0 + CHUNK_, N_);
  float s = 0.f, ss = 0.f;
  const float* base = g_h2 + ((size_t)b * N_) * E2_ + t;
  for (int n = n0; n < n1; n++) {
    float v = base[(size_t)n * E2_];
    s += v;
    ss = fmaf(v, v, ss);
  }
  g_ps [(b * NCH_ + ch) * E2_ + t] = s;
  g_pss[(b * NCH_ + ch) * E2_ + t] = ss;
}

// ---- kernel B2: finalize per-(batch,channel) scale/shift ----
__global__ __launch_bounds__(256) void kB2(const float* __restrict__ gamma,
                                           const float* __restrict__ beta) {
  int b = blockIdx.x, t = threadIdx.x;
  float s = 0.f, ss = 0.f;
  for (int ch = 0; ch < NCH_; ch++) {
    s  += g_ps [(b * NCH_ + ch) * E2_ + t];
    ss += g_pss[(b * NCH_ + ch) * E2_ + t];
  }
  float mean = s * (1.f / N_);
  float var  = ss * (1.f / N_) - mean * mean;
  float inv  = rsqrtf(var + EPS_);
  float sc = inv * gamma[t];
  g_scale[b * E2_ + t] = sc;
  g_shift[b * E2_ + t] = beta[t] - mean * sc;
}

// ---- kernel C: norm, layers 3-4, fill + scatter output row ----
__global__ __launch_bounds__(256) void kC(const float* __restrict__ b3,
                                          const float* __restrict__ b4,
                                          float* __restrict__ out) {
  int r = blockIdx.x, tid = threadIdx.x;
  int b = r / N_;

  __shared__ float hns[E2_];
  __shared__ float4 p2[256];
  __shared__ float h3s[EMB_];
  __shared__ float part[128];

  float v = g_h2[(size_t)r * E2_ + tid];
  hns[tid] = fmaf(v, g_scale[b * E2_ + tid], g_shift[b * E2_ + tid]);

  int myidx = 0;
  float myval = 0.f;
  if (tid < K_) myidx = g_si[r * K_ + tid];
  __syncthreads();

  // ---- layer 3: 256 -> 128, relu (float4, 4 outputs/thread, 8 c-segments) ----
  {
    int og = tid & 31, seg = tid >> 5;
    const float4* W3t4 = reinterpret_cast<const float4*>(g_W3t);
    float4 acc = make_float4(0.f, 0.f, 0.f, 0.f);
    int c0 = seg * 32;
    #pragma unroll
    for (int cc = 0; cc < 32; cc++) {
      int c = c0 + cc;
      float h = hns[c];
      float4 w = W3t4[c * 32 + og];
      acc.x = fmaf(h, w.x, acc.x);
      acc.y = fmaf(h, w.y, acc.y);
      acc.z = fmaf(h, w.z, acc.z);
      acc.w = fmaf(h, w.w, acc.w);
    }
    p2[tid] = acc;
  }
  __syncthreads();
  if (tid < 32) {
    float4 s = p2[tid];
    #pragma unroll
    for (int g = 1; g < 8; g++) {
      float4 q = p2[tid + 32 * g];
      s.x += q.x; s.y += q.y; s.z += q.z; s.w += q.w;
    }
    float4 bb = reinterpret_cast<const float4*>(b3)[tid];
    float4 o;
    o.x = fmaxf(s.x + bb.x, 0.f);
    o.y = fmaxf(s.y + bb.y, 0.f);
    o.z = fmaxf(s.z + bb.z, 0.f);
    o.w = fmaxf(s.w + bb.w, 0.f);
    reinterpret_cast<float4*>(h3s)[tid] = o;
  }
  __syncthreads();

  // ---- layer 4: 128 -> 16 (8 segments of 16 c, then combine) ----
  if (tid < 128) {
    int k = tid & 15, seg = tid >> 4;
    float acc = 0.f;
    int c0 = seg * 16;
    #pragma unroll
    for (int cc = 0; cc < 16; cc++) {
      int c = c0 + cc;
      acc = fmaf(h3s[c], g_W4t[c * 16 + k], acc);
    }
    part[tid] = acc;
  }
  __syncthreads();
  if (tid < K_) {
    float a = b4[tid];
    #pragma unroll
    for (int s = 0; s < 8; s++) a += part[tid + 16 * s];
    myval = a - g_sd[r * K_ + tid];
  }

  // ---- fill row with PENALTY (float4), then scatter 16 values ----
  float4* orow4 = reinterpret_cast<float4*>(out + (size_t)r * M_);
  float4 pen = make_float4(PENALTY_, PENALTY_, PENALTY_, PENALTY_);
  for (int i = tid; i < M_ / 4; i += 256) orow4[i] = pen;
  __syncthreads();
  if (tid < K_) out[(size_t)r * M_ + myidx] = myval;
}

extern "C" void kernel_launch(void* const* d_in, const int* in_sizes, int n_in,
                              void* d_out, int out_size) {
  const float* theta = (const float*)d_in[0];
  const float* dist  = (const float*)d_in[1];
  const float* insf  = (const float*)d_in[2];
  const float* W1    = (const float*)d_in[3];
  const float* b1    = (const float*)d_in[4];
  const float* W2    = (const float*)d_in[5];
  const float* b2    = (const float*)d_in[6];
  const float* W3    = (const float*)d_in[7];
  const float* b3    = (const float*)d_in[8];
  const float* W4    = (const float*)d_in[9];
  const float* b4    = (const float*)d_in[10];
  const float* gamma = (const float*)d_in[11];
  const float* beta  = (const float*)d_in[12];
  float* out = (float*)d_out;

  kT<<<72, 256>>>(W1, W2, W3, W4);
  kA<<<R_, 256>>>(theta, dist, insf, b1, b2);
  kB1<<<dim3(NCH_, B_), 256>>>();
  kB2<<<B_, 256>>>(gamma, beta);
  kC<<<R_, 256>>>(b3, b4, out);
}

// round 2
// speedup vs baseline: 1.3337x; 1.3337x over previous
#include <cuda_runtime.h>
#include <cstdint>

#define B_   4
#define N_   2000
#define M_   2000
#define R_   8000      // B*N rows
#define K_   16
#define EMB_ 128
#define E2_  256
#define PENALTY_ (-10.0f)
#define EPS_ 1e-5f
#define TAU_ 0.05f
#define CAP_ 1024
#define NCH_ 32
#define CHUNK_ 63

typedef unsigned long long ull;

// ---- packed f32x2 helpers (FFMA2: 2x fma-pipe throughput, PTX-only) ----
__device__ __forceinline__ ull fma2(ull a, ull b, ull c) {
  ull d;
  asm("fma.rn.f32x2 %0, %1, %2, %3;" : "=l"(d) : "l"(a), "l"(b), "l"(c));
  return d;
}
__device__ __forceinline__ ull add2(ull a, ull b) {
  ull d;
  asm("add.rn.f32x2 %0, %1, %2;" : "=l"(d) : "l"(a), "l"(b));
  return d;
}
__device__ __forceinline__ ull packdup(float x) {
  ull r;
  asm("mov.b64 %0, {%1, %1};" : "=l"(r) : "f"(x));
  return r;
}
__device__ __forceinline__ void unpack2(ull v, float& x, float& y) {
  asm("mov.b64 {%0, %1}, %2;" : "=f"(x), "=f"(y) : "l"(v));
}

// ---- scratch (static device globals: no runtime allocation) ----
__device__ __align__(16) float g_W1t[34 * 128];        // W1^T  [j][co]
__device__ __align__(16) float g_W2t[128 * 256];       // W2^T  [c][co]
__device__ __align__(16) float g_W3t[256 * 128];       // W3^T  [c][co]
__device__ __align__(16) float g_W4t[128 * 16];        // W4^T  [c][k]
__device__ __align__(16) float g_h2[(size_t)R_ * E2_]; // layer-2 activations
__device__ float g_sd[R_ * K_];          // normalized sorted dist
__device__ int   g_si[R_ * K_];          // sorted indices
__device__ float g_ps [B_ * NCH_ * E2_]; // partial sums
__device__ float g_pss[B_ * NCH_ * E2_]; // partial sum-of-squares
__device__ float g_scale[B_ * E2_];
__device__ float g_shift[B_ * E2_];
__device__ int   g_bcnt;                 // last-block counter (self-resetting)

// ---- kernel T: transpose the four weight matrices ----
__global__ __launch_bounds__(256) void kT(const float* __restrict__ W1,
                                          const float* __restrict__ W2,
                                          const float* __restrict__ W3,
                                          const float* __restrict__ W4) {
  int t = blockIdx.x * blockDim.x + threadIdx.x;
  int stride = gridDim.x * blockDim.x;
  for (int o = t; o < 34 * 128; o += stride) { int co = o & 127, j = o >> 7; g_W1t[o] = W1[co * 34 + j]; }
  for (int o = t; o < 128 * 256; o += stride) { int co = o & 255, c = o >> 8; g_W2t[o] = W2[co * 128 + c]; }
  for (int o = t; o < 256 * 128; o += stride) { int co = o & 127, c = o >> 7; g_W3t[o] = W3[co * 256 + c]; }
  for (int o = t; o < 128 * 16;  o += stride) { int k  = o & 15,  c = o >> 4; g_W4t[o] = W4[k * 128 + c]; }
}

// ---- kernel A: top-16 (filter + rank-select), layers 1-2 ----
__global__ __launch_bounds__(256) void kA(const float* __restrict__ theta,
                                          const float* __restrict__ dist,
                                          const float* __restrict__ insf,
                                          const float* __restrict__ b1,
                                          const float* __restrict__ b2) {
  int r = blockIdx.x;
  int tid = threadIdx.x;

  __shared__ ull cand[CAP_];
  __shared__ int cnt;
  __shared__ float sds[K_];
  __shared__ int   sis[K_];
  __shared__ float xs[34];
  __shared__ float h1s[EMB_];
  __shared__ ull p2[256];
  __shared__ ull wred[8];

  if (tid == 0) cnt = 0;
  __syncthreads();

  // ---- filter pass: float4 loads, candidates with dist < TAU ----
  const float4* drow4 = reinterpret_cast<const float4*>(dist + (size_t)r * M_);
  for (int i4 = tid; i4 < M_ / 4; i4 += 256) {
    float4 v = drow4[i4];
    int base = i4 * 4;
    if (v.x < TAU_) { int p = atomicAdd(&cnt, 1); if (p < CAP_) cand[p] = (((ull)__float_as_uint(v.x)) << 32) | (unsigned)(base + 0); }
    if (v.y < TAU_) { int p = atomicAdd(&cnt, 1); if (p < CAP_) cand[p] = (((ull)__float_as_uint(v.y)) << 32) | (unsigned)(base + 1); }
    if (v.z < TAU_) { int p = atomicAdd(&cnt, 1); if (p < CAP_) cand[p] = (((ull)__float_as_uint(v.z)) << 32) | (unsigned)(base + 2); }
    if (v.w < TAU_) { int p = atomicAdd(&cnt, 1); if (p < CAP_) cand[p] = (((ull)__float_as_uint(v.w)) << 32) | (unsigned)(base + 3); }
  }
  __syncthreads();
  int C = cnt;

  if (C >= K_ && C <= CAP_) {
    // ---- rank-based select: keys are unique, rank = #strictly smaller ----
    for (int i = tid; i < C; i += 256) {
      ull key = cand[i];
      int rank = 0;
      for (int j = 0; j < C; j++) rank += (cand[j] < key);
      if (rank < K_) {
        sds[rank] = __uint_as_float((unsigned)(key >> 32));
        sis[rank] = (int)(unsigned)(key & 0xffffffffu);
      }
    }
  } else {
    // ---- exact fallback (never taken on benchmark data) ----
    const float* drow = dist + (size_t)r * M_;
    ull last = 0ULL;
    int wid = tid >> 5, lane = tid & 31;
    for (int k = 0; k < K_; k++) {
      ull m = ~0ULL;
      for (int i = tid; i < M_; i += 256) {
        ull c = (((ull)__float_as_uint(drow[i])) << 32) | (unsigned)i;
        if ((k == 0 || c > last) && c < m) m = c;
      }
      #pragma unroll
      for (int off = 16; off; off >>= 1) {
        ull o = __shfl_down_sync(0xffffffffu, m, off);
        m = (o < m) ? o : m;
      }
      if (lane == 0) wred[wid] = m;
      __syncthreads();
      if (tid == 0) {
        m = wred[0];
        for (int w = 1; w < 8; w++) if (wred[w] < m) m = wred[w];
        wred[0] = m;
        sds[k] = __uint_as_float((unsigned)(m >> 32));
        sis[k] = (int)(unsigned)(m & 0xffffffffu);
      }
      __syncthreads();
      last = wred[0];
      __syncthreads();
    }
  }
  __syncthreads();

  // ---- build x = [sorted_dist/max, sorted_theta, ins0, ins1] ----
  if (tid < K_) {
    float maxd = sds[K_ - 1];
    float nd = sds[tid] / maxd;
    xs[tid] = nd;
    xs[K_ + tid] = theta[(size_t)r * M_ + sis[tid]];
    g_sd[r * K_ + tid] = nd;
    g_si[r * K_ + tid] = sis[tid];
  }
  if (tid == 32) xs[32] = insf[r];
  if (tid == 33) xs[33] = insf[R_ + r];
  __syncthreads();

  // ---- layer 1: 34 -> 128, relu (scalar, small) ----
  if (tid < EMB_) {
    float acc = b1[tid];
    #pragma unroll
    for (int j = 0; j < 34; j++) acc = fmaf(xs[j], g_W1t[j * EMB_ + tid], acc);
    h1s[tid] = fmaxf(acc, 0.f);
  }
  __syncthreads();

  // ---- layer 2: 128 -> 256, relu (f32x2, 1 output-pair/thread, 2 c-segments) ----
  {
    int pr = tid & 127, seg = tid >> 7;       // pair 0..127, seg 0..1
    const ull* W2p = reinterpret_cast<const ull*>(g_W2t);
    ull acc = 0ULL;
    int c0 = seg * 64;
    #pragma unroll
    for (int cc = 0; cc < 64; cc++) {
      int c = c0 + cc;
      acc = fma2(packdup(h1s[c]), W2p[c * 128 + pr], acc);
    }
    p2[tid] = acc;
  }
  __syncthreads();
  if (tid < 128) {
    ull s = add2(p2[tid], p2[tid + 128]);
    float sx, sy;
    unpack2(s, sx, sy);
    float2 bb = reinterpret_cast<const float2*>(b2)[tid];
    float2 o;
    o.x = fmaxf(sx + bb.x, 0.f);
    o.y = fmaxf(sy + bb.y, 0.f);
    reinterpret_cast<float2*>(g_h2)[(size_t)r * 128 + tid] = o;
  }
}

// ---- kernel B: InstanceNorm partial sums + fused last-block finalize ----
__global__ __launch_bounds__(256) void kB(const float* __restrict__ gamma,
                                          const float* __restrict__ beta) {
  int ch = blockIdx.x & 31, b = blockIdx.x >> 5, t = threadIdx.x;
  int n0 = ch * CHUNK_;
  int n1 = min(n0 + CHUNK_, N_);
  float s = 0.f, ss = 0.f;
  const float* base = g_h2 + ((size_t)b * N_) * E2_ + t;
  for (int n = n0; n < n1; n++) {
    float v = base[(size_t)n * E2_];
    s += v;
    ss = fmaf(v, v, ss);
  }
  g_ps [(b * NCH_ + ch) * E2_ + t] = s;
  g_pss[(b * NCH_ + ch) * E2_ + t] = ss;

  __threadfence();
  __shared__ int isLast;
  if (t == 0) isLast = (atomicAdd(&g_bcnt, 1) == B_ * NCH_ - 1) ? 1 : 0;
  __syncthreads();
  if (!isLast) return;
  if (t == 0) g_bcnt = 0;   // reset for next graph replay

  for (int bb = 0; bb < B_; bb++) {
    float sf = 0.f, ssf = 0.f;
    for (int c2 = 0; c2 < NCH_; c2++) {
      sf  += g_ps [(bb * NCH_ + c2) * E2_ + t];
      ssf += g_pss[(bb * NCH_ + c2) * E2_ + t];
    }
    float mean = sf * (1.f / N_);
    float var  = ssf * (1.f / N_) - mean * mean;
    float inv  = rsqrtf(var + EPS_);
    float sc = inv * gamma[t];
    g_scale[bb * E2_ + t] = sc;
    g_shift[bb * E2_ + t] = beta[t] - mean * sc;
  }
}

// ---- kernel C: norm, layers 3-4, fill + scatter output row ----
__global__ __launch_bounds__(256) void kC(const float* __restrict__ b3,
                                          const float* __restrict__ b4,
                                          float* __restrict__ out) {
  int r = blockIdx.x, tid = threadIdx.x;
  int b = r / N_;

  __shared__ float hns[E2_];
  __shared__ ull p2[256];
  __shared__ float h3s[EMB_];
  __shared__ float part[128];

  float v = g_h2[(size_t)r * E2_ + tid];
  hns[tid] = fmaf(v, g_scale[b * E2_ + tid], g_shift[b * E2_ + tid]);

  int myidx = 0;
  float myval = 0.f;
  if (tid < K_) myidx = g_si[r * K_ + tid];
  __syncthreads();

  // ---- layer 3: 256 -> 128, relu (f32x2, 1 pair/thread, 4 c-segments) ----
  {
    int pr = tid & 63, seg = tid >> 6;        // pair 0..63, seg 0..3
    const ull* W3p = reinterpret_cast<const ull*>(g_W3t);
    ull acc = 0ULL;
    int c0 = seg * 64;
    #pragma unroll
    for (int cc = 0; cc < 64; cc++) {
      int c = c0 + cc;
      acc = fma2(packdup(hns[c]), W3p[c * 64 + pr], acc);
    }
    p2[tid] = acc;
  }
  __syncthreads();
  if (tid < 64) {
    ull s = add2(add2(p2[tid], p2[tid + 64]), add2(p2[tid + 128], p2[tid + 192]));
    float sx, sy;
    unpack2(s, sx, sy);
    float2 bb = reinterpret_cast<const float2*>(b3)[tid];
    h3s[2 * tid + 0] = fmaxf(sx + bb.x, 0.f);
    h3s[2 * tid + 1] = fmaxf(sy + bb.y, 0.f);
  }
  __syncthreads();

  // ---- layer 4: 128 -> 16 (8 segments of 16 c, then combine) ----
  if (tid < 128) {
    int k = tid & 15, seg = tid >> 4;
    float acc = 0.f;
    int c0 = seg * 16;
    #pragma unroll
    for (int cc = 0; cc < 16; cc++) {
      int c = c0 + cc;
      acc = fmaf(h3s[c], g_W4t[c * 16 + k], acc);
    }
    part[tid] = acc;
  }
  __syncthreads();
  if (tid < K_) {
    float a = b4[tid];
    #pragma unroll
    for (int s = 0; s < 8; s++) a += part[tid + 16 * s];
    myval = a - g_sd[r * K_ + tid];
  }

  // ---- fill row with PENALTY (float4), then scatter 16 values ----
  float4* orow4 = reinterpret_cast<float4*>(out + (size_t)r * M_);
  float4 pen = make_float4(PENALTY_, PENALTY_, PENALTY_, PENALTY_);
  for (int i = tid; i < M_ / 4; i += 256) orow4[i] = pen;
  __syncthreads();
  if (tid < K_) out[(size_t)r * M_ + myidx] = myval;
}

extern "C" void kernel_launch(void* const* d_in, const int* in_sizes, int n_in,
                              void* d_out, int out_size) {
  const float* theta = (const float*)d_in[0];
  const float* dist  = (const float*)d_in[1];
  const float* insf  = (const float*)d_in[2];
  const float* W1    = (const float*)d_in[3];
  const float* b1    = (const float*)d_in[4];
  const float* W2    = (const float*)d_in[5];
  const float* b2    = (const float*)d_in[6];
  const float* W3    = (const float*)d_in[7];
  const float* b3    = (const float*)d_in[8];
  const float* W4    = (const float*)d_in[9];
  const float* b4    = (const float*)d_in[10];
  const float* gamma = (const float*)d_in[11];
  const float* beta  = (const float*)d_in[12];
  float* out = (float*)d_out;

  kT<<<72, 256>>>(W1, W2, W3, W4);
  kA<<<R_, 256>>>(theta, dist, insf, b1, b2);
  kB<<<B_ * NCH_, 256>>>(gamma, beta);
  kC<<<R_, 256>>>(b3, b4, out);
}

// round 3
// speedup vs baseline: 1.6666x; 1.2496x over previous
#include <cuda_runtime.h>
#include <cstdint>

#define B_   4
#define N_   2000
#define M_   2000
#define R_   8000      // B*N rows
#define K_   16
#define EMB_ 128
#define E2_  256
#define PENALTY_ (-10.0f)
#define EPS_ 1e-5f
#define TAU_ 0.05f
#define CAP_ 256       // per-row candidate cap (mean 100, sd 9.8 -> >CAP is ~16 sigma)
#define RPB_ 8         // rows per block
#define GA_  (R_ / RPB_)
#define NCH_ 64
#define CHUNK_ 32

typedef unsigned long long ull;

// ---- packed f32x2 helpers (FFMA2: 2x fma-pipe throughput, PTX-only) ----
__device__ __forceinline__ ull fma2(ull a, ull b, ull c) {
  ull d;
  asm("fma.rn.f32x2 %0, %1, %2, %3;" : "=l"(d) : "l"(a), "l"(b), "l"(c));
  return d;
}
__device__ __forceinline__ ull add2(ull a, ull b) {
  ull d;
  asm("add.rn.f32x2 %0, %1, %2;" : "=l"(d) : "l"(a), "l"(b));
  return d;
}
__device__ __forceinline__ ull packdup(float x) {
  ull r;
  asm("mov.b64 %0, {%1, %1};" : "=l"(r) : "f"(x));
  return r;
}
__device__ __forceinline__ void unpack2(ull v, float& x, float& y) {
  asm("mov.b64 {%0, %1}, %2;" : "=f"(x), "=f"(y) : "l"(v));
}

// ---- scratch (static device globals: no runtime allocation) ----
__device__ __align__(16) float g_W1t[34 * 128];        // W1^T  [j][co]
__device__ __align__(16) float g_W2t[128 * 256];       // W2^T  [c][co]
__device__ __align__(16) float g_W3t[256 * 128];       // W3^T  [c][co]
__device__ __align__(16) float g_W4t[128 * 16];        // W4^T  [c][k]
__device__ __align__(16) float g_h2[(size_t)R_ * E2_]; // layer-2 activations
__device__ float g_sd[R_ * K_];          // normalized sorted dist
__device__ int   g_si[R_ * K_];          // sorted indices
__device__ float g_ps [B_ * NCH_ * E2_]; // partial sums
__device__ float g_pss[B_ * NCH_ * E2_]; // partial sum-of-squares
__device__ float g_scale[B_ * E2_];
__device__ float g_shift[B_ * E2_];
__device__ int   g_bcnt;                 // last-block counter (self-resetting)

// ---- kernel T: transpose the four weight matrices ----
__global__ __launch_bounds__(256) void kT(const float* __restrict__ W1,
                                          const float* __restrict__ W2,
                                          const float* __restrict__ W3,
                                          const float* __restrict__ W4) {
  int t = blockIdx.x * blockDim.x + threadIdx.x;
  int stride = gridDim.x * blockDim.x;
  for (int o = t; o < 34 * 128; o += stride) { int co = o & 127, j = o >> 7; g_W1t[o] = W1[co * 34 + j]; }
  for (int o = t; o < 128 * 256; o += stride) { int co = o & 255, c = o >> 8; g_W2t[o] = W2[co * 128 + c]; }
  for (int o = t; o < 256 * 128; o += stride) { int co = o & 127, c = o >> 7; g_W3t[o] = W3[co * 256 + c]; }
  for (int o = t; o < 128 * 16;  o += stride) { int k  = o & 15,  c = o >> 4; g_W4t[o] = W4[k * 128 + c]; }
}

// ---- kernel A: 8 rows/block; warp-per-row top-16, then layers 1-2 ----
__global__ __launch_bounds__(256) void kA(const float* __restrict__ theta,
                                          const float* __restrict__ dist,
                                          const float* __restrict__ insf,
                                          const float* __restrict__ b1,
                                          const float* __restrict__ b2) {
  int r0 = blockIdx.x * RPB_;
  int tid = threadIdx.x, wid = tid >> 5, lane = tid & 31;

  __shared__ ull cand[RPB_][CAP_];                 // 16KB
  __shared__ int cnt[RPB_];
  __shared__ float sds[RPB_][K_];
  __shared__ int   sis[RPB_][K_];
  __shared__ float xs[RPB_][34];
  __shared__ __align__(16) float h1t[128][RPB_];   // transposed [c][row], 4KB
  __shared__ ull p2[2][128][RPB_];                 // seg partials, 16KB

  if (tid < RPB_) cnt[tid] = 0;
  __syncthreads();

  // ---- filter: warp wid scans row r0+wid (float4, coalesced) ----
  {
    int r = r0 + wid;
    const float4* drow4 = reinterpret_cast<const float4*>(dist + (size_t)r * M_);
    for (int i4 = lane; i4 < M_ / 4; i4 += 32) {
      float4 v = drow4[i4];
      int base = i4 * 4;
      if (v.x < TAU_) { int p = atomicAdd(&cnt[wid], 1); if (p < CAP_) cand[wid][p] = (((ull)__float_as_uint(v.x)) << 32) | (unsigned)(base + 0); }
      if (v.y < TAU_) { int p = atomicAdd(&cnt[wid], 1); if (p < CAP_) cand[wid][p] = (((ull)__float_as_uint(v.y)) << 32) | (unsigned)(base + 1); }
      if (v.z < TAU_) { int p = atomicAdd(&cnt[wid], 1); if (p < CAP_) cand[wid][p] = (((ull)__float_as_uint(v.z)) << 32) | (unsigned)(base + 2); }
      if (v.w < TAU_) { int p = atomicAdd(&cnt[wid], 1); if (p < CAP_) cand[wid][p] = (((ull)__float_as_uint(v.w)) << 32) | (unsigned)(base + 3); }
    }
  }
  __syncwarp();
  int C = cnt[wid];

  if (C >= K_ && C <= CAP_) {
    // ---- rank-select within the warp (keys unique -> ranks are a permutation) ----
    for (int i = lane; i < C; i += 32) {
      ull key = cand[wid][i];
      int rank = 0;
      for (int j = 0; j < C; j++) rank += (cand[wid][j] < key);
      if (rank < K_) {
        sds[wid][rank] = __uint_as_float((unsigned)(key >> 32));
        sis[wid][rank] = (int)(unsigned)(key & 0xffffffffu);
      }
    }
  } else {
    // ---- warp fallback: exact 16-pass min (never taken on benchmark data) ----
    int r = r0 + wid;
    const float* drow = dist + (size_t)r * M_;
    ull last = 0ULL;
    for (int k = 0; k < K_; k++) {
      ull m = ~0ULL;
      for (int i = lane; i < M_; i += 32) {
        ull c = (((ull)__float_as_uint(drow[i])) << 32) | (unsigned)i;
        if ((k == 0 || c > last) && c < m) m = c;
      }
      #pragma unroll
      for (int off = 16; off; off >>= 1) {
        ull o = __shfl_down_sync(0xffffffffu, m, off);
        m = (o < m) ? o : m;
      }
      m = __shfl_sync(0xffffffffu, m, 0);
      if (lane == 0) {
        sds[wid][k] = __uint_as_float((unsigned)(m >> 32));
        sis[wid][k] = (int)(unsigned)(m & 0xffffffffu);
      }
      last = m;
    }
  }
  __syncwarp();

  // ---- build x = [sorted_dist/max, sorted_theta, ins0, ins1] per row ----
  if (lane < K_) {
    int r = r0 + wid;
    float maxd = sds[wid][K_ - 1];
    float nd = sds[wid][lane] / maxd;
    xs[wid][lane] = nd;
    xs[wid][K_ + lane] = theta[(size_t)r * M_ + sis[wid][lane]];
    g_sd[r * K_ + lane] = nd;
    g_si[r * K_ + lane] = sis[wid][lane];
  }
  if (lane == 16) xs[wid][32] = insf[r0 + wid];
  if (lane == 17) xs[wid][33] = insf[R_ + r0 + wid];
  __syncthreads();

  // ---- layer 1: 34 -> 128, relu; weight col loaded once, 4 rows per thread ----
  {
    int co = tid & 127, rg = (tid >> 7) * 4;
    float bb = b1[co];
    float a0 = bb, a1 = bb, a2 = bb, a3 = bb;
    #pragma unroll
    for (int j = 0; j < 34; j++) {
      float w = g_W1t[j * 128 + co];
      a0 = fmaf(xs[rg + 0][j], w, a0);
      a1 = fmaf(xs[rg + 1][j], w, a1);
      a2 = fmaf(xs[rg + 2][j], w, a2);
      a3 = fmaf(xs[rg + 3][j], w, a3);
    }
    h1t[co][rg + 0] = fmaxf(a0, 0.f);
    h1t[co][rg + 1] = fmaxf(a1, 0.f);
    h1t[co][rg + 2] = fmaxf(a2, 0.f);
    h1t[co][rg + 3] = fmaxf(a3, 0.f);
  }
  __syncthreads();

  // ---- layer 2: 128 -> 256 for 8 rows; weight pair loaded once per thread ----
  {
    int pr = tid & 127, seg = tid >> 7;
    int c0 = seg * 64;
    const ull* W2p = reinterpret_cast<const ull*>(g_W2t);
    ull acc[RPB_];
    #pragma unroll
    for (int r = 0; r < RPB_; r++) acc[r] = 0ULL;
    #pragma unroll 8
    for (int cc = 0; cc < 64; cc++) {
      int c = c0 + cc;
      ull w = W2p[c * 128 + pr];
      float4 ha = *reinterpret_cast<const float4*>(&h1t[c][0]);
      float4 hb = *reinterpret_cast<const float4*>(&h1t[c][4]);
      acc[0] = fma2(packdup(ha.x), w, acc[0]);
      acc[1] = fma2(packdup(ha.y), w, acc[1]);
      acc[2] = fma2(packdup(ha.z), w, acc[2]);
      acc[3] = fma2(packdup(ha.w), w, acc[3]);
      acc[4] = fma2(packdup(hb.x), w, acc[4]);
      acc[5] = fma2(packdup(hb.y), w, acc[5]);
      acc[6] = fma2(packdup(hb.z), w, acc[6]);
      acc[7] = fma2(packdup(hb.w), w, acc[7]);
    }
    #pragma unroll
    for (int r = 0; r < RPB_; r++) p2[seg][pr][r] = acc[r];
  }
  __syncthreads();
  if (tid < 128) {
    float2 bb = reinterpret_cast<const float2*>(b2)[tid];
    #pragma unroll
    for (int r = 0; r < RPB_; r++) {
      ull s = add2(p2[0][tid][r], p2[1][tid][r]);
      float sx, sy;
      unpack2(s, sx, sy);
      float2 o;
      o.x = fmaxf(sx + bb.x, 0.f);
      o.y = fmaxf(sy + bb.y, 0.f);
      reinterpret_cast<float2*>(g_h2)[(size_t)(r0 + r) * 128 + tid] = o;
    }
  }
}

// ---- kernel B: InstanceNorm partial sums + fused last-block finalize ----
__global__ __launch_bounds__(256) void kB(const float* __restrict__ gamma,
                                          const float* __restrict__ beta) {
  int ch = blockIdx.x & (NCH_ - 1), b = blockIdx.x / NCH_, t = threadIdx.x;
  int n0 = ch * CHUNK_;
  int n1 = min(n0 + CHUNK_, N_);
  float s = 0.f, ss = 0.f;
  const float* base = g_h2 + ((size_t)b * N_) * E2_ + t;
  for (int n = n0; n < n1; n++) {
    float v = base[(size_t)n * E2_];
    s += v;
    ss = fmaf(v, v, ss);
  }
  g_ps [(b * NCH_ + ch) * E2_ + t] = s;
  g_pss[(b * NCH_ + ch) * E2_ + t] = ss;

  __threadfence();
  __shared__ int isLast;
  if (t == 0) isLast = (atomicAdd(&g_bcnt, 1) == B_ * NCH_ - 1) ? 1 : 0;
  __syncthreads();
  if (!isLast) return;
  if (t == 0) g_bcnt = 0;   // reset for next graph replay

  for (int bb = 0; bb < B_; bb++) {
    float sf = 0.f, ssf = 0.f;
    for (int c2 = 0; c2 < NCH_; c2++) {
      sf  += g_ps [(bb * NCH_ + c2) * E2_ + t];
      ssf += g_pss[(bb * NCH_ + c2) * E2_ + t];
    }
    float mean = sf * (1.f / N_);
    float var  = ssf * (1.f / N_) - mean * mean;
    float inv  = rsqrtf(var + EPS_);
    float sc = inv * gamma[t];
    g_scale[bb * E2_ + t] = sc;
    g_shift[bb * E2_ + t] = beta[t] - mean * sc;
  }
}

// ---- kernel C: 8 rows/block; norm, layers 3-4, fill + scatter ----
__global__ __launch_bounds__(256) void kC(const float* __restrict__ b3,
                                          const float* __restrict__ b4,
                                          float* __restrict__ out) {
  int r0 = blockIdx.x * RPB_;
  int tid = threadIdx.x;
  int b = r0 / N_;   // RPB_ divides N_, so block never crosses batch boundary

  __shared__ __align__(16) float hn[E2_][RPB_];    // normalized acts [c][row], 8KB
  __shared__ ull p3[4][64][RPB_];                  // seg partials, 16KB
  __shared__ __align__(16) float h3t[EMB_][RPB_];  // layer-3 out [c][row], 4KB
  __shared__ float part[2][128];

  // ---- fill 8 contiguous rows with PENALTY first (STGs drain under compute) ----
  {
    float4* o4 = reinterpret_cast<float4*>(out + (size_t)r0 * M_);
    float4 pen = make_float4(PENALTY_, PENALTY_, PENALTY_, PENALTY_);
    for (int i = tid; i < RPB_ * M_ / 4; i += 256) o4[i] = pen;
  }

  // ---- load h2 + instance-norm (scale/shift cached per channel) ----
  {
    float sc = g_scale[b * E2_ + tid];
    float sh = g_shift[b * E2_ + tid];
    #pragma unroll
    for (int r = 0; r < RPB_; r++) {
      float v = g_h2[(size_t)(r0 + r) * E2_ + tid];
      hn[tid][r] = fmaf(v, sc, sh);
    }
  }
  __syncthreads();

  // ---- layer 3: 256 -> 128 for 8 rows (64 pairs x 4 c-segments) ----
  {
    int pr = tid & 63, seg = tid >> 6;
    int c0 = seg * 64;
    const ull* W3p = reinterpret_cast<const ull*>(g_W3t);
    ull acc[RPB_];
    #pragma unroll
    for (int r = 0; r < RPB_; r++) acc[r] = 0ULL;
    #pragma unroll 8
    for (int cc = 0; cc < 64; cc++) {
      int c = c0 + cc;
      ull w = W3p[c * 64 + pr];
      float4 ha = *reinterpret_cast<const float4*>(&hn[c][0]);
      float4 hb = *reinterpret_cast<const float4*>(&hn[c][4]);
      acc[0] = fma2(packdup(ha.x), w, acc[0]);
      acc[1] = fma2(packdup(ha.y), w, acc[1]);
      acc[2] = fma2(packdup(ha.z), w, acc[2]);
      acc[3] = fma2(packdup(ha.w), w, acc[3]);
      acc[4] = fma2(packdup(hb.x), w, acc[4]);
      acc[5] = fma2(packdup(hb.y), w, acc[5]);
      acc[6] = fma2(packdup(hb.z), w, acc[6]);
      acc[7] = fma2(packdup(hb.w), w, acc[7]);
    }
    #pragma unroll
    for (int r = 0; r < RPB_; r++) p3[seg][pr][r] = acc[r];
  }
  __syncthreads();
  if (tid < 64) {
    float2 bb = reinterpret_cast<const float2*>(b3)[tid];
    #pragma unroll
    for (int r = 0; r < RPB_; r++) {
      ull s = add2(add2(p3[0][tid][r], p3[1][tid][r]),
                   add2(p3[2][tid][r], p3[3][tid][r]));
      float sx, sy;
      unpack2(s, sx, sy);
      h3t[2 * tid + 0][r] = fmaxf(sx + bb.x, 0.f);
      h3t[2 * tid + 1][r] = fmaxf(sy + bb.y, 0.f);
    }
  }
  __syncthreads();

  // ---- layer 4: 128 -> 16 per row (2 c-segments of 64) ----
  {
    int rk = tid & 127, seg = tid >> 7;
    int row = rk >> 4, k = rk & 15;
    int c0 = seg * 64;
    float acc = 0.f;
    #pragma unroll 8
    for (int cc = 0; cc < 64; cc++) {
      int c = c0 + cc;
      acc = fmaf(h3t[c][row], g_W4t[c * 16 + k], acc);
    }
    part[seg][rk] = acc;
  }
  __syncthreads();

  // ---- combine, subtract sorted_dist, scatter (fill already complete) ----
  if (tid < 128) {
    int row = tid >> 4, k = tid & 15;
    int r = r0 + row;
    float val = part[0][tid] + part[1][tid] + b4[k] - g_sd[r * K_ + k];
    int idx = g_si[r * K_ + k];
    out[(size_t)r * M_ + idx] = val;
  }
}

extern "C" void kernel_launch(void* const* d_in, const int* in_sizes, int n_in,
                              void* d_out, int out_size) {
  const float* theta = (const float*)d_in[0];
  const float* dist  = (const float*)d_in[1];
  const float* insf  = (const float*)d_in[2];
  const float* W1    = (const float*)d_in[3];
  const float* b1    = (const float*)d_in[4];
  const float* W2    = (const float*)d_in[5];
  const float* b2    = (const float*)d_in[6];
  const float* W3    = (const float*)d_in[7];
  const float* b3    = (const float*)d_in[8];
  const float* W4    = (const float*)d_in[9];
  const float* b4    = (const float*)d_in[10];
  const float* gamma = (const float*)d_in[11];
  const float* beta  = (const float*)d_in[12];
  float* out = (float*)d_out;

  kT<<<72, 256>>>(W1, W2, W3, W4);
  kA<<<GA_, 256>>>(theta, dist, insf, b1, b2);
  kB<<<B_ * NCH_, 256>>>(gamma, beta);
  kC<<<GA_, 256>>>(b3, b4, out);
}

// round 4
// speedup vs baseline: 1.8108x; 1.0865x over previous
#include <cuda_runtime.h>
#include <cstdint>

#define B_   4
#define N_   2000
#define M_   2000
#define R_   8000      // B*N rows
#define K_   16
#define EMB_ 128
#define E2_  256
#define PENALTY_ (-10.0f)
#define EPS_ 1e-5f
#define TAU_ 0.035f
#define CAP_ 128       // E[C]=70, sd 8.2 -> overflow ~7 sigma; underflow <16 ~6.6 sigma
#define RPB_ 8         // rows per block
#define GA_  (R_ / RPB_)   // 1000
#define BPB_ (GA_ / B_)    // 250 blocks per batch
#define SCH_ 8             // sum-chunks per batch in kB

typedef unsigned long long ull;

// ---- packed f32x2 helpers (FFMA2: 2x fma-pipe throughput, PTX-only) ----
__device__ __forceinline__ ull fma2(ull a, ull b, ull c) {
  ull d;
  asm("fma.rn.f32x2 %0, %1, %2, %3;" : "=l"(d) : "l"(a), "l"(b), "l"(c));
  return d;
}
__device__ __forceinline__ ull add2(ull a, ull b) {
  ull d;
  asm("add.rn.f32x2 %0, %1, %2;" : "=l"(d) : "l"(a), "l"(b));
  return d;
}
__device__ __forceinline__ ull packdup(float x) {
  ull r;
  asm("mov.b64 %0, {%1, %1};" : "=l"(r) : "f"(x));
  return r;
}
__device__ __forceinline__ void unpack2(ull v, float& x, float& y) {
  asm("mov.b64 {%0, %1}, %2;" : "=f"(x), "=f"(y) : "l"(v));
}

// ---- scratch (static device globals: no runtime allocation) ----
__device__ __align__(16) float g_W1t[34 * 128];        // W1^T  [j][co]
__device__ __align__(16) float g_W2t[128 * 256];       // W2^T  [c][co]
__device__ __align__(16) float g_W3t[256 * 128];       // W3^T  [c][co]
__device__ __align__(16) float g_W4t[128 * 16];        // W4^T  [c][k]
__device__ __align__(16) float g_h2[(size_t)R_ * E2_]; // layer-2 activations
__device__ float g_sd[R_ * K_];            // normalized sorted dist
__device__ int   g_si[R_ * K_];            // sorted indices
__device__ float g_psA [GA_ * E2_];        // per-block channel sums (from kA)
__device__ float g_pssA[GA_ * E2_];        // per-block channel sum-of-squares
__device__ float g_ps [B_ * SCH_ * E2_];   // stage-2 partials
__device__ float g_pss[B_ * SCH_ * E2_];
__device__ float g_scale[B_ * E2_];
__device__ float g_shift[B_ * E2_];
__device__ int   g_bcnt;                   // last-block counter (self-resetting)

// ---- kernel T: transpose the four weight matrices ----
__global__ __launch_bounds__(256) void kT(const float* __restrict__ W1,
                                          const float* __restrict__ W2,
                                          const float* __restrict__ W3,
                                          const float* __restrict__ W4) {
  int t = blockIdx.x * blockDim.x + threadIdx.x;
  int stride = gridDim.x * blockDim.x;
  for (int o = t; o < 34 * 128; o += stride) { int co = o & 127, j = o >> 7; g_W1t[o] = W1[co * 34 + j]; }
  for (int o = t; o < 128 * 256; o += stride) { int co = o & 255, c = o >> 8; g_W2t[o] = W2[co * 128 + c]; }
  for (int o = t; o < 256 * 128; o += stride) { int co = o & 127, c = o >> 7; g_W3t[o] = W3[co * 256 + c]; }
  for (int o = t; o < 128 * 16;  o += stride) { int k  = o & 15,  c = o >> 4; g_W4t[o] = W4[k * 128 + c]; }
}

// ---- kernel A: 8 rows/block; fill, warp-per-row top-16, layers 1-2, norm partials ----
__global__ __launch_bounds__(256) void kA(const float* __restrict__ theta,
                                          const float* __restrict__ dist,
                                          const float* __restrict__ insf,
                                          const float* __restrict__ b1,
                                          const float* __restrict__ b2,
                                          float* __restrict__ out) {
  int blk = blockIdx.x;
  int r0 = blk * RPB_;
  int tid = threadIdx.x, wid = tid >> 5, lane = tid & 31;

  __shared__ ull cand[RPB_][CAP_];                 // 8KB
  __shared__ float sds[RPB_][K_];
  __shared__ int   sis[RPB_][K_];
  __shared__ float xs[RPB_][34];
  __shared__ __align__(16) float h1t[128][RPB_];   // transposed [c][row], 4KB
  __shared__ ull p2[2][128][RPB_];                 // seg partials, 16KB

  // ---- fill this block's 8 output rows with PENALTY (drains under compute) ----
  {
    float4* o4 = reinterpret_cast<float4*>(out + (size_t)r0 * M_);
    float4 pen = make_float4(PENALTY_, PENALTY_, PENALTY_, PENALTY_);
    for (int i = tid; i < RPB_ * M_ / 4; i += 256) o4[i] = pen;
  }

  // ---- filter: warp wid scans row r0+wid; ballot-aggregated emission (no atomics) ----
  int C;
  {
    int r = r0 + wid;
    const float4* drow4 = reinterpret_cast<const float4*>(dist + (size_t)r * M_);
    unsigned lmlt = (1u << lane) - 1u;
    int cbase = 0;
    #pragma unroll 4
    for (int it = 0; it < (M_ / 4 + 31) / 32; it++) {
      int i4 = it * 32 + lane;
      bool valid = i4 < M_ / 4;
      float4 v = valid ? drow4[valid ? i4 : 0]
                       : make_float4(1.f, 1.f, 1.f, 1.f);
      int base = i4 * 4;
      unsigned m;
      m = __ballot_sync(0xffffffffu, valid && v.x < TAU_);
      if (valid && v.x < TAU_) { int p = cbase + __popc(m & lmlt); if (p < CAP_) cand[wid][p] = (((ull)__float_as_uint(v.x)) << 32) | (unsigned)(base + 0); }
      cbase += __popc(m);
      m = __ballot_sync(0xffffffffu, valid && v.y < TAU_);
      if (valid && v.y < TAU_) { int p = cbase + __popc(m & lmlt); if (p < CAP_) cand[wid][p] = (((ull)__float_as_uint(v.y)) << 32) | (unsigned)(base + 1); }
      cbase += __popc(m);
      m = __ballot_sync(0xffffffffu, valid && v.z < TAU_);
      if (valid && v.z < TAU_) { int p = cbase + __popc(m & lmlt); if (p < CAP_) cand[wid][p] = (((ull)__float_as_uint(v.z)) << 32) | (unsigned)(base + 2); }
      cbase += __popc(m);
      m = __ballot_sync(0xffffffffu, valid && v.w < TAU_);
      if (valid && v.w < TAU_) { int p = cbase + __popc(m & lmlt); if (p < CAP_) cand[wid][p] = (((ull)__float_as_uint(v.w)) << 32) | (unsigned)(base + 3); }
      cbase += __popc(m);
    }
    C = cbase;   // uniform across the warp
  }
  __syncwarp();

  if (C >= K_ && C <= CAP_) {
    // ---- rank-select within the warp (keys unique -> ranks are a permutation) ----
    for (int i = lane; i < C; i += 32) {
      ull key = cand[wid][i];
      int rank = 0;
      for (int j = 0; j < C; j++) rank += (cand[wid][j] < key);
      if (rank < K_) {
        sds[wid][rank] = __uint_as_float((unsigned)(key >> 32));
        sis[wid][rank] = (int)(unsigned)(key & 0xffffffffu);
      }
    }
  } else {
    // ---- warp fallback: exact 16-pass min (probability ~1e-7 per run) ----
    int r = r0 + wid;
    const float* drow = dist + (size_t)r * M_;
    ull last = 0ULL;
    for (int k = 0; k < K_; k++) {
      ull m = ~0ULL;
      for (int i = lane; i < M_; i += 32) {
        ull c = (((ull)__float_as_uint(drow[i])) << 32) | (unsigned)i;
        if ((k == 0 || c > last) && c < m) m = c;
      }
      #pragma unroll
      for (int off = 16; off; off >>= 1) {
        ull o = __shfl_down_sync(0xffffffffu, m, off);
        m = (o < m) ? o : m;
      }
      m = __shfl_sync(0xffffffffu, m, 0);
      if (lane == 0) {
        sds[wid][k] = __uint_as_float((unsigned)(m >> 32));
        sis[wid][k] = (int)(unsigned)(m & 0xffffffffu);
      }
      last = m;
    }
  }
  __syncwarp();

  // ---- build x = [sorted_dist/max, sorted_theta, ins0, ins1] per row ----
  if (lane < K_) {
    int r = r0 + wid;
    float maxd = sds[wid][K_ - 1];
    float nd = sds[wid][lane] / maxd;
    xs[wid][lane] = nd;
    xs[wid][K_ + lane] = theta[(size_t)r * M_ + sis[wid][lane]];
    g_sd[r * K_ + lane] = nd;
    g_si[r * K_ + lane] = sis[wid][lane];
  }
  if (lane == 16) xs[wid][32] = insf[r0 + wid];
  if (lane == 17) xs[wid][33] = insf[R_ + r0 + wid];
  __syncthreads();

  // ---- layer 1: 34 -> 128, relu; weight col loaded once, 4 rows per thread ----
  {
    int co = tid & 127, rg = (tid >> 7) * 4;
    float bb = b1[co];
    float a0 = bb, a1 = bb, a2 = bb, a3 = bb;
    #pragma unroll
    for (int j = 0; j < 34; j++) {
      float w = g_W1t[j * 128 + co];
      a0 = fmaf(xs[rg + 0][j], w, a0);
      a1 = fmaf(xs[rg + 1][j], w, a1);
      a2 = fmaf(xs[rg + 2][j], w, a2);
      a3 = fmaf(xs[rg + 3][j], w, a3);
    }
    h1t[co][rg + 0] = fmaxf(a0, 0.f);
    h1t[co][rg + 1] = fmaxf(a1, 0.f);
    h1t[co][rg + 2] = fmaxf(a2, 0.f);
    h1t[co][rg + 3] = fmaxf(a3, 0.f);
  }
  __syncthreads();

  // ---- layer 2: 128 -> 256 for 8 rows; weight pair loaded once per thread ----
  {
    int pr = tid & 127, seg = tid >> 7;
    int c0 = seg * 64;
    const ull* W2p = reinterpret_cast<const ull*>(g_W2t);
    ull acc[RPB_];
    #pragma unroll
    for (int r = 0; r < RPB_; r++) acc[r] = 0ULL;
    #pragma unroll 8
    for (int cc = 0; cc < 64; cc++) {
      int c = c0 + cc;
      ull w = W2p[c * 128 + pr];
      float4 ha = *reinterpret_cast<const float4*>(&h1t[c][0]);
      float4 hb = *reinterpret_cast<const float4*>(&h1t[c][4]);
      acc[0] = fma2(packdup(ha.x), w, acc[0]);
      acc[1] = fma2(packdup(ha.y), w, acc[1]);
      acc[2] = fma2(packdup(ha.z), w, acc[2]);
      acc[3] = fma2(packdup(ha.w), w, acc[3]);
      acc[4] = fma2(packdup(hb.x), w, acc[4]);
      acc[5] = fma2(packdup(hb.y), w, acc[5]);
      acc[6] = fma2(packdup(hb.z), w, acc[6]);
      acc[7] = fma2(packdup(hb.w), w, acc[7]);
    }
    #pragma unroll
    for (int r = 0; r < RPB_; r++) p2[seg][pr][r] = acc[r];
  }
  __syncthreads();
  // ---- epilogue: bias+relu, store h2, and channel partial sums for InstanceNorm ----
  if (tid < 128) {
    float2 bb = reinterpret_cast<const float2*>(b2)[tid];
    float s0 = 0.f, s1 = 0.f, q0 = 0.f, q1 = 0.f;
    #pragma unroll
    for (int r = 0; r < RPB_; r++) {
      ull s = add2(p2[0][tid][r], p2[1][tid][r]);
      float sx, sy;
      unpack2(s, sx, sy);
      float2 o;
      o.x = fmaxf(sx + bb.x, 0.f);
      o.y = fmaxf(sy + bb.y, 0.f);
      reinterpret_cast<float2*>(g_h2)[(size_t)(r0 + r) * 128 + tid] = o;
      s0 += o.x; q0 = fmaf(o.x, o.x, q0);
      s1 += o.y; q1 = fmaf(o.y, o.y, q1);
    }
    g_psA [blk * E2_ + 2 * tid + 0] = s0;
    g_psA [blk * E2_ + 2 * tid + 1] = s1;
    g_pssA[blk * E2_ + 2 * tid + 0] = q0;
    g_pssA[blk * E2_ + 2 * tid + 1] = q1;
  }
}

// ---- kernel B: reduce per-block partials -> per-(batch,channel) scale/shift ----
__global__ __launch_bounds__(256) void kB(const float* __restrict__ gamma,
                                          const float* __restrict__ beta) {
  int blk = blockIdx.x;              // 32 blocks: (batch b, chunk s)
  int b = blk >> 3, s = blk & 7;
  int t = threadIdx.x;
  int i0 = s * 32, i1 = min(i0 + 32, BPB_);
  float sum = 0.f, sq = 0.f;
  for (int i = i0; i < i1; i++) {
    int pb = b * BPB_ + i;
    sum += g_psA [pb * E2_ + t];
    sq  += g_pssA[pb * E2_ + t];
  }
  g_ps [(b * SCH_ + s) * E2_ + t] = sum;
  g_pss[(b * SCH_ + s) * E2_ + t] = sq;

  __threadfence();
  __shared__ int isLast;
  if (t == 0) isLast = (atomicAdd(&g_bcnt, 1) == B_ * SCH_ - 1) ? 1 : 0;
  __syncthreads();
  if (!isLast) return;
  if (t == 0) g_bcnt = 0;   // reset for next graph replay

  for (int bb = 0; bb < B_; bb++) {
    float sf = 0.f, ssf = 0.f;
    #pragma unroll
    for (int c2 = 0; c2 < SCH_; c2++) {
      sf  += g_ps [(bb * SCH_ + c2) * E2_ + t];
      ssf += g_pss[(bb * SCH_ + c2) * E2_ + t];
    }
    float mean = sf * (1.f / N_);
    float var  = ssf * (1.f / N_) - mean * mean;
    float inv  = rsqrtf(var + EPS_);
    float sc = inv * gamma[t];
    g_scale[bb * E2_ + t] = sc;
    g_shift[bb * E2_ + t] = beta[t] - mean * sc;
  }
}

// ---- kernel C: 8 rows/block; norm, layers 3-4, scatter (fill done in kA) ----
__global__ __launch_bounds__(256, 6) void kC(const float* __restrict__ b3,
                                             const float* __restrict__ b4,
                                             float* __restrict__ out) {
  int r0 = blockIdx.x * RPB_;
  int tid = threadIdx.x;
  int b = r0 / N_;   // RPB_ divides N_, so block never crosses batch boundary

  __shared__ __align__(16) float hn[E2_][RPB_];    // normalized acts [c][row], 8KB
  __shared__ ull p3[4][64][RPB_];                  // seg partials, 16KB
  __shared__ __align__(16) float h3t[EMB_][RPB_];  // layer-3 out [c][row], 4KB
  __shared__ float part[2][128];

  // ---- load h2 + instance-norm (scale/shift cached per channel) ----
  {
    float sc = g_scale[b * E2_ + tid];
    float sh = g_shift[b * E2_ + tid];
    #pragma unroll
    for (int r = 0; r < RPB_; r++) {
      float v = g_h2[(size_t)(r0 + r) * E2_ + tid];
      hn[tid][r] = fmaf(v, sc, sh);
    }
  }
  __syncthreads();

  // ---- layer 3: 256 -> 128 for 8 rows (64 pairs x 4 c-segments) ----
  {
    int pr = tid & 63, seg = tid >> 6;
    int c0 = seg * 64;
    const ull* W3p = reinterpret_cast<const ull*>(g_W3t);
    ull acc[RPB_];
    #pragma unroll
    for (int r = 0; r < RPB_; r++) acc[r] = 0ULL;
    #pragma unroll 8
    for (int cc = 0; cc < 64; cc++) {
      int c = c0 + cc;
      ull w = W3p[c * 64 + pr];
      float4 ha = *reinterpret_cast<const float4*>(&hn[c][0]);
      float4 hb = *reinterpret_cast<const float4*>(&hn[c][4]);
      acc[0] = fma2(packdup(ha.x), w, acc[0]);
      acc[1] = fma2(packdup(ha.y), w, acc[1]);
      acc[2] = fma2(packdup(ha.z), w, acc[2]);
      acc[3] = fma2(packdup(ha.w), w, acc[3]);
      acc[4] = fma2(packdup(hb.x), w, acc[4]);
      acc[5] = fma2(packdup(hb.y), w, acc[5]);
      acc[6] = fma2(packdup(hb.z), w, acc[6]);
      acc[7] = fma2(packdup(hb.w), w, acc[7]);
    }
    #pragma unroll
    for (int r = 0; r < RPB_; r++) p3[seg][pr][r] = acc[r];
  }
  __syncthreads();
  if (tid < 64) {
    float2 bb = reinterpret_cast<const float2*>(b3)[tid];
    #pragma unroll
    for (int r = 0; r < RPB_; r++) {
      ull s = add2(add2(p3[0][tid][r], p3[1][tid][r]),
                   add2(p3[2][tid][r], p3[3][tid][r]));
      float sx, sy;
      unpack2(s, sx, sy);
      h3t[2 * tid + 0][r] = fmaxf(sx + bb.x, 0.f);
      h3t[2 * tid + 1][r] = fmaxf(sy + bb.y, 0.f);
    }
  }
  __syncthreads();

  // ---- layer 4: 128 -> 16 per row (2 c-segments of 64) ----
  {
    int rk = tid & 127, seg = tid >> 7;
    int row = rk >> 4, k = rk & 15;
    int c0 = seg * 64;
    float acc = 0.f;
    #pragma unroll 8
    for (int cc = 0; cc < 64; cc++) {
      int c = c0 + cc;
      acc = fmaf(h3t[c][row], g_W4t[c * 16 + k], acc);
    }
    part[seg][rk] = acc;
  }
  __syncthreads();

  // ---- combine, subtract sorted_dist, scatter (fill already done in kA) ----
  if (tid < 128) {
    int row = tid >> 4, k = tid & 15;
    int r = r0 + row;
    float val = part[0][tid] + part[1][tid] + b4[k] - g_sd[r * K_ + k];
    int idx = g_si[r * K_ + k];
    out[(size_t)r * M_ + idx] = val;
  }
}

extern "C" void kernel_launch(void* const* d_in, const int* in_sizes, int n_in,
                              void* d_out, int out_size) {
  const float* theta = (const float*)d_in[0];
  const float* dist  = (const float*)d_in[1];
  const float* insf  = (const float*)d_in[2];
  const float* W1    = (const float*)d_in[3];
  const float* b1    = (const float*)d_in[4];
  const float* W2    = (const float*)d_in[5];
  const float* b2    = (const float*)d_in[6];
  const float* W3    = (const float*)d_in[7];
  const float* b3    = (const float*)d_in[8];
  const float* W4    = (const float*)d_in[9];
  const float* b4    = (const float*)d_in[10];
  const float* gamma = (const float*)d_in[11];
  const float* beta  = (const float*)d_in[12];
  float* out = (float*)d_out;

  kT<<<72, 256>>>(W1, W2, W3, W4);
  kA<<<GA_, 256>>>(theta, dist, insf, b1, b2, out);
  kB<<<B_ * SCH_, 256>>>(gamma, beta);
  kC<<<GA_, 256>>>(b3, b4, out);
}